// round 15
// baseline (speedup 1.0000x reference)
#include <cuda_runtime.h>

#define IMG_H 1024
#define IMG_W 1024
#define N_IMG 16
#define WV (IMG_W / 4)            // float4 columns per row = 256
#define PAIRS_PER_IMG (IMG_H / 2) // 512

__device__ __forceinline__ void process_row(
    const float4& wc4, const float4& wu4, const float4& wd4,
    const float4& bc4, const float4& bu4, const float4& bd4,
    const float4& tc4,
    const float* __restrict__ wrow, const float* __restrict__ brow,
    int xv, float4& ow, float4& ob)
{
    const float TS   = 0.0001f;
    const float PRE  = 1.845f;
    const float WEFF = 0.449f;
    const float SEEP = 0.2f;
    const float ETA  = 3.0f;
    const float MORT = 0.3f;
    const float D3   = 0.05f;

    const unsigned FULL = 0xFFFFFFFFu;
    int lane = xv & 31;

    // Horizontal halo via warp shuffle (warp covers 32 contiguous float4s)
    float wl = __shfl_up_sync(FULL, wc4.w, 1);
    float bl = __shfl_up_sync(FULL, bc4.w, 1);
    float wr = __shfl_down_sync(FULL, wc4.x, 1);
    float br = __shfl_down_sync(FULL, bc4.x, 1);
    if (lane == 0) {
        wl = (xv > 0) ? __ldg(wrow + xv * 4 - 1) : wc4.x;
        bl = (xv > 0) ? __ldg(brow + xv * 4 - 1) : bc4.x;
    }
    if (lane == 31) {
        wr = (xv < WV - 1) ? __ldg(wrow + xv * 4 + 4) : wc4.w;
        br = (xv < WV - 1) ? __ldg(brow + xv * 4 + 4) : bc4.w;
    }

    float wc[4] = {wc4.x, wc4.y, wc4.z, wc4.w};
    float bc[4] = {bc4.x, bc4.y, bc4.z, bc4.w};
    float wu[4] = {wu4.x, wu4.y, wu4.z, wu4.w};
    float wd[4] = {wd4.x, wd4.y, wd4.z, wd4.w};
    float bu[4] = {bu4.x, bu4.y, bu4.z, bu4.w};
    float bd[4] = {bd4.x, bd4.y, bd4.z, bd4.w};
    float tc[4] = {tc4.x, tc4.y, tc4.z, tc4.w};
    float wL[4] = {wl,    wc[0], wc[1], wc[2]};
    float wR[4] = {wc[1], wc[2], wc[3], wr   };
    float bL[4] = {bl,    bc[0], bc[1], bc[2]};
    float bR[4] = {bc[1], bc[2], bc[3], br   };

    float wn[4], bn[4];
#pragma unroll
    for (int i = 0; i < 4; ++i) {
        float lapw = wu[i] + wd[i] + wL[i] + wR[i] - 4.0f * wc[i];
        float lapb = bu[i] + bd[i] + bL[i] + bR[i] - 4.0f * bc[i];
        float uptake = wc[i] * bc[i] * fmaf(ETA, bc[i], 1.0f);
        float dw = (lapw - SEEP * wc[i] + PRE - uptake) * TS;
        float db = (D3 * lapb - MORT * tc[i] * bc[i] + WEFF * uptake) * TS;
        wn[i] = wc[i] + dw;
        bn[i] = bc[i] + db;
    }
    ow = make_float4(wn[0], wn[1], wn[2], wn[3]);
    ob = make_float4(bn[0], bn[1], bn[2], bn[3]);
}

__global__ void __launch_bounds__(128)
nca_step_kernel(const float4* __restrict__ w4,
                const float4* __restrict__ b4,
                const float4* __restrict__ T4,
                float4* __restrict__ out_w,
                float4* __restrict__ out_b)
{
    // Block = 128 threads = half a row (128 float4 columns), two rows (a pair).
    int half = blockIdx.x & 1;
    int pair = (blockIdx.x >> 1) & (PAIRS_PER_IMG - 1);
    int n    = blockIdx.x >> 10;               // / (2*512)

    int xv = half * 128 + threadIdx.x;         // global float4 column 0..255

    int y0 = pair * 2;
    int y1 = y0 + 1;
    int ym = (y0 > 0)          ? y0 - 1 : 0;
    int yp = (y1 < IMG_H - 1)  ? y1 + 1 : IMG_H - 1;

    int base = n * IMG_H * WV;
    int i_m = base + ym * WV + xv;
    int i_0 = base + y0 * WV + xv;
    int i_1 = i_0 + WV;
    int i_p = base + yp * WV + xv;

    // Front-batched loads (MLP_p1 = 10). T is read-once: evict-first so it
    // doesn't displace w/b halo lines in L2.
    float4 w_m = w4[i_m];
    float4 w_0 = w4[i_0];
    float4 w_1 = w4[i_1];
    float4 w_p = w4[i_p];
    float4 b_m = b4[i_m];
    float4 b_0 = b4[i_0];
    float4 b_1 = b4[i_1];
    float4 b_p = b4[i_p];
    float4 t_0 = __ldcs(&T4[i_0]);
    float4 t_1 = __ldcs(&T4[i_1]);

    const float* wrow0 = reinterpret_cast<const float*>(w4 + base + y0 * WV);
    const float* brow0 = reinterpret_cast<const float*>(b4 + base + y0 * WV);
    const float* wrow1 = wrow0 + IMG_W;
    const float* brow1 = brow0 + IMG_W;

    float4 ow0, ob0, ow1, ob1;
    process_row(w_0, w_m, w_1, b_0, b_m, b_1, t_0, wrow0, brow0, xv, ow0, ob0);
    process_row(w_1, w_0, w_p, b_1, b_0, b_p, t_1, wrow1, brow1, xv, ow1, ob1);

    // Streaming stores: write-only data, keep it out of L2
    __stcs(&out_w[i_0], ow0);
    __stcs(&out_w[i_1], ow1);
    __stcs(&out_b[i_0], ob0);
    __stcs(&out_b[i_1], ob1);
}

extern "C" void kernel_launch(void* const* d_in, const int* in_sizes, int n_in,
                              void* d_out, int out_size)
{
    const float4* w4 = (const float4*)d_in[0];
    const float4* b4 = (const float4*)d_in[1];
    const float4* T4 = (const float4*)d_in[2];

    const int n_elem = N_IMG * IMG_H * IMG_W;
    float4* out_w = (float4*)d_out;
    float4* out_b = (float4*)((float*)d_out + n_elem);

    const int grid = N_IMG * PAIRS_PER_IMG * 2;  // 16384 blocks of 128
    nca_step_kernel<<<grid, 128>>>(w4, b4, T4, out_w, out_b);
}

// round 16
// speedup vs baseline: 1.0390x; 1.0390x over previous
#include <cuda_runtime.h>

#define IMG_H 1024
#define IMG_W 1024
#define N_IMG 16
#define WV (IMG_W / 4)            // float4 columns per row = 256
#define PAIRS_PER_IMG (IMG_H / 2) // 512

__device__ __forceinline__ void process_row(
    const float4& wc4, const float4& wu4, const float4& wd4,
    const float4& bc4, const float4& bu4, const float4& bd4,
    const float4& tc4,
    const float* __restrict__ wrow, const float* __restrict__ brow,
    int xv, float4& ow, float4& ob)
{
    const float TS   = 0.0001f;
    const float PRE  = 1.845f;
    const float WEFF = 0.449f;
    const float SEEP = 0.2f;
    const float ETA  = 3.0f;
    const float MORT = 0.3f;
    const float D3   = 0.05f;

    const unsigned FULL = 0xFFFFFFFFu;
    int lane = xv & 31;

    // Horizontal halo via warp shuffle (warp covers 32 contiguous float4s)
    float wl = __shfl_up_sync(FULL, wc4.w, 1);
    float bl = __shfl_up_sync(FULL, bc4.w, 1);
    float wr = __shfl_down_sync(FULL, wc4.x, 1);
    float br = __shfl_down_sync(FULL, bc4.x, 1);
    if (lane == 0) {
        wl = (xv > 0) ? __ldg(wrow + xv * 4 - 1) : wc4.x;
        bl = (xv > 0) ? __ldg(brow + xv * 4 - 1) : bc4.x;
    }
    if (lane == 31) {
        wr = (xv < WV - 1) ? __ldg(wrow + xv * 4 + 4) : wc4.w;
        br = (xv < WV - 1) ? __ldg(brow + xv * 4 + 4) : bc4.w;
    }

    float wc[4] = {wc4.x, wc4.y, wc4.z, wc4.w};
    float bc[4] = {bc4.x, bc4.y, bc4.z, bc4.w};
    float wu[4] = {wu4.x, wu4.y, wu4.z, wu4.w};
    float wd[4] = {wd4.x, wd4.y, wd4.z, wd4.w};
    float bu[4] = {bu4.x, bu4.y, bu4.z, bu4.w};
    float bd[4] = {bd4.x, bd4.y, bd4.z, bd4.w};
    float tc[4] = {tc4.x, tc4.y, tc4.z, tc4.w};
    float wL[4] = {wl,    wc[0], wc[1], wc[2]};
    float wR[4] = {wc[1], wc[2], wc[3], wr   };
    float bL[4] = {bl,    bc[0], bc[1], bc[2]};
    float bR[4] = {bc[1], bc[2], bc[3], br   };

    float wn[4], bn[4];
#pragma unroll
    for (int i = 0; i < 4; ++i) {
        float lapw = wu[i] + wd[i] + wL[i] + wR[i] - 4.0f * wc[i];
        float lapb = bu[i] + bd[i] + bL[i] + bR[i] - 4.0f * bc[i];
        float uptake = wc[i] * bc[i] * fmaf(ETA, bc[i], 1.0f);
        float dw = (lapw - SEEP * wc[i] + PRE - uptake) * TS;
        float db = (D3 * lapb - MORT * tc[i] * bc[i] + WEFF * uptake) * TS;
        wn[i] = wc[i] + dw;
        bn[i] = bc[i] + db;
    }
    ow = make_float4(wn[0], wn[1], wn[2], wn[3]);
    ob = make_float4(bn[0], bn[1], bn[2], bn[3]);
}

__global__ void __launch_bounds__(128)
nca_step_kernel(const float4* __restrict__ w4,
                const float4* __restrict__ b4,
                const float4* __restrict__ T4,
                float4* __restrict__ out_w,
                float4* __restrict__ out_b)
{
    // Block = 128 threads = half a row (128 float4 columns), two rows (a pair).
    int half = blockIdx.x & 1;
    int pair = (blockIdx.x >> 1) & (PAIRS_PER_IMG - 1);
    int n    = blockIdx.x >> 10;               // / (2*512)

    int xv = half * 128 + threadIdx.x;         // global float4 column 0..255

    int y0 = pair * 2;
    int y1 = y0 + 1;
    int ym = (y0 > 0)          ? y0 - 1 : 0;
    int yp = (y1 < IMG_H - 1)  ? y1 + 1 : IMG_H - 1;

    int base = n * IMG_H * WV;
    int i_m = base + ym * WV + xv;
    int i_0 = base + y0 * WV + xv;
    int i_1 = i_0 + WV;
    int i_p = base + yp * WV + xv;

    // Front-batched loads (MLP_p1 = 10). T is read-once: evict-first so it
    // doesn't displace w/b halo lines in L2.
    float4 w_m = w4[i_m];
    float4 w_0 = w4[i_0];
    float4 w_1 = w4[i_1];
    float4 w_p = w4[i_p];
    float4 b_m = b4[i_m];
    float4 b_0 = b4[i_0];
    float4 b_1 = b4[i_1];
    float4 b_p = b4[i_p];
    float4 t_0 = __ldcs(&T4[i_0]);
    float4 t_1 = __ldcs(&T4[i_1]);

    const float* wrow0 = reinterpret_cast<const float*>(w4 + base + y0 * WV);
    const float* brow0 = reinterpret_cast<const float*>(b4 + base + y0 * WV);
    const float* wrow1 = wrow0 + IMG_W;
    const float* brow1 = brow0 + IMG_W;

    float4 ow0, ob0, ow1, ob1;
    process_row(w_0, w_m, w_1, b_0, b_m, b_1, t_0, wrow0, brow0, xv, ow0, ob0);
    process_row(w_1, w_0, w_p, b_1, b_0, b_p, t_1, wrow1, brow1, xv, ow1, ob1);

    // Streaming stores: write-only data, keep it out of L2
    __stcs(&out_w[i_0], ow0);
    __stcs(&out_w[i_1], ow1);
    __stcs(&out_b[i_0], ob0);
    __stcs(&out_b[i_1], ob1);
}

extern "C" void kernel_launch(void* const* d_in, const int* in_sizes, int n_in,
                              void* d_out, int out_size)
{
    const float4* w4 = (const float4*)d_in[0];
    const float4* b4 = (const float4*)d_in[1];
    const float4* T4 = (const float4*)d_in[2];

    const int n_elem = N_IMG * IMG_H * IMG_W;
    float4* out_w = (float4*)d_out;
    float4* out_b = (float4*)((float*)d_out + n_elem);

    const int grid = N_IMG * PAIRS_PER_IMG * 2;  // 16384 blocks of 128
    nca_step_kernel<<<grid, 128>>>(w4, b4, T4, out_w, out_b);
}